// round 2
// baseline (speedup 1.0000x reference)
#include <cuda_runtime.h>
#include <cuda_bf16.h>
#include <math.h>

// Problem constants (fixed by setup_inputs)
#define PB 2
#define PT 2048
#define PC 2048
#define PH 16
#define PD 128
#define PM (PB*PT)        // 4096 rows of x
#define PHD (PH*PD)       // 2048

// ---------------- scratch (device globals; no allocs allowed) ----------------
__device__ float g_q[PB*PT*PH*PD];
__device__ float g_k[PB*PT*PH*PD];
__device__ float g_v[PB*PT*PH*PD];
__device__ float g_y[PB*PT*PH*PD];
__device__ float g_lf[PB*PH*PT];
__device__ float g_cf[PB*PH*PT];

// ---------------- SGEMM: C[M,N] = A[M,K] @ B[K,N], fp32 ----------------
// BM=BN=128, BK=16, 256 threads, 8x8 per thread. M%128==0, N%128==0, K%16==0.
__global__ __launch_bounds__(256) void sgemm128(const float* __restrict__ A,
                                                const float* __restrict__ B,
                                                float* __restrict__ C,
                                                int M, int N, int K)
{
    __shared__ float As[16][128];   // [k][m]
    __shared__ float Bs[16][128];   // [k][n]
    const int tid = threadIdx.x;
    const int bm = blockIdx.y * 128;
    const int bn = blockIdx.x * 128;
    const int tx = tid & 15;        // col group
    const int ty = tid >> 4;        // row group

    float acc[8][8];
#pragma unroll
    for (int r = 0; r < 8; r++)
#pragma unroll
        for (int c = 0; c < 8; c++) acc[r][c] = 0.f;

    const int arow = tid >> 2;           // 0..63
    const int acol = (tid & 3) << 2;     // 0,4,8,12
    const int brow = tid >> 5;           // 0..7
    const int bcol = (tid & 31) << 2;    // 0..124

    for (int k0 = 0; k0 < K; k0 += 16) {
#pragma unroll
        for (int i = 0; i < 2; i++) {
            int r = arow + 64 * i;
            float4 a = *(const float4*)&A[(size_t)(bm + r) * K + k0 + acol];
            As[acol + 0][r] = a.x;
            As[acol + 1][r] = a.y;
            As[acol + 2][r] = a.z;
            As[acol + 3][r] = a.w;
        }
#pragma unroll
        for (int i = 0; i < 2; i++) {
            int r = brow + 8 * i;
            *(float4*)&Bs[r][bcol] = *(const float4*)&B[(size_t)(k0 + r) * N + bn + bcol];
        }
        __syncthreads();
#pragma unroll
        for (int kk = 0; kk < 16; kk++) {
            float4 a0 = *(const float4*)&As[kk][ty * 8];
            float4 a1 = *(const float4*)&As[kk][ty * 8 + 4];
            float4 b0 = *(const float4*)&Bs[kk][tx * 8];
            float4 b1 = *(const float4*)&Bs[kk][tx * 8 + 4];
            float ar[8] = {a0.x, a0.y, a0.z, a0.w, a1.x, a1.y, a1.z, a1.w};
            float br[8] = {b0.x, b0.y, b0.z, b0.w, b1.x, b1.y, b1.z, b1.w};
#pragma unroll
            for (int r = 0; r < 8; r++)
#pragma unroll
                for (int c = 0; c < 8; c++) acc[r][c] += ar[r] * br[c];
        }
        __syncthreads();
    }
#pragma unroll
    for (int r = 0; r < 8; r++) {
        size_t o = (size_t)(bm + ty * 8 + r) * N + bn + tx * 8;
        float4 c0 = make_float4(acc[r][0], acc[r][1], acc[r][2], acc[r][3]);
        float4 c1 = make_float4(acc[r][4], acc[r][5], acc[r][6], acc[r][7]);
        *(float4*)&C[o] = c0;
        *(float4*)&C[o + 4] = c1;
    }
}

// ---------------- gate kernel: lam/logit/log_fgate per (b,t,h) ----------------
__global__ __launch_bounds__(256) void gate_kernel(const float* __restrict__ x,
                                                   const float* __restrict__ fw,
                                                   const float* __restrict__ fb,
                                                   const float* __restrict__ wl,
                                                   float* __restrict__ lf)
{
    __shared__ float xs[2048];
    __shared__ float red[256];
    __shared__ float dots[32];
    const int bt = blockIdx.x;
    const int tid = threadIdx.x;
    const float* xr = x + (size_t)bt * PC;
#pragma unroll
    for (int i = 0; i < 2; i++)
        *(float4*)&xs[(tid + 256 * i) * 4] = *(const float4*)&xr[(tid + 256 * i) * 4];
    __syncthreads();

    const int g = tid >> 5, o = tid & 31;
    const float* W = (o < 16) ? fw : wl;
    const int h = o & 15;
    float s = 0.f;
    for (int c = g; c < PC; c += 8) s += xs[c] * W[c * PH + h];
    red[tid] = s;
    __syncthreads();
    if (tid < 32) {
        float t = red[tid];
#pragma unroll
        for (int g2 = 1; g2 < 8; g2++) t += red[tid + 32 * g2];
        dots[tid] = t;
    }
    __syncthreads();
    if (tid < 16) {
        const int b = bt >> 11;       // /T
        const int t = bt & (PT - 1);
        float fdot = dots[tid] + fb[tid];
        float ldot = dots[16 + tid];
        float lam = ldot > 0.f ? ldot + 1.f : expf(ldot);  // elu(x)+1
        float logit = fdot * lam;
        float ls = (logit >= 0.f) ? -log1pf(expf(-logit))
                                  : (logit - log1pf(expf(logit)));
        lf[((size_t)(b * PH + tid)) * PT + t] = ls / (lam + 0.001f);
    }
}

// ---------------- cumsum over T per (b,h) ----------------
__global__ __launch_bounds__(256) void cumsum_kernel(const float* __restrict__ lf,
                                                     float* __restrict__ cf)
{
    __shared__ float tot[256];
    const int bh = blockIdx.x, tid = threadIdx.x;
    const float* in = lf + (size_t)bh * PT;
    float* out = cf + (size_t)bh * PT;
    float v[8];
    float r = 0.f;
#pragma unroll
    for (int j = 0; j < 8; j++) { r += in[tid * 8 + j]; v[j] = r; }
    tot[tid] = r;
    __syncthreads();
    for (int off = 1; off < 256; off <<= 1) {
        float t = 0.f;
        if (tid >= off) t = tot[tid - off];
        __syncthreads();
        if (tid >= off) tot[tid] += t;
        __syncthreads();
    }
    float base = tid ? tot[tid - 1] : 0.f;
#pragma unroll
    for (int j = 0; j < 8; j++) out[tid * 8 + j] = v[j] + base;
}

// ---------------- RoPE + RMSNorm, in place on [B,T,H,D] ----------------
__global__ __launch_bounds__(256) void rope_rms_kernel(float* __restrict__ data,
                                                       const float* __restrict__ cosp,
                                                       const float* __restrict__ sinp)
{
    const int wid = blockIdx.x * 8 + (threadIdx.x >> 5);   // (b,t,h) index
    const int lane = threadIdx.x & 31;
    const int t = (wid >> 4) & (PT - 1);
    float* row = data + (size_t)wid * PD;
    const int i0 = lane, i1 = lane + 32;
    float x1a = row[i0], x1b = row[i1];
    float x2a = row[i0 + 64], x2b = row[i1 + 64];
    float ca = cosp[t * 64 + i0], cb = cosp[t * 64 + i1];
    float sa = sinp[t * 64 + i0], sb = sinp[t * 64 + i1];
    float o0 = x1a * ca + x2a * sa;
    float o1 = x1b * cb + x2b * sb;
    float o2 = x2a * ca - x1a * sa;
    float o3 = x2b * cb - x1b * sb;
    float ss = o0 * o0 + o1 * o1 + o2 * o2 + o3 * o3;
#pragma unroll
    for (int off = 16; off > 0; off >>= 1) ss += __shfl_xor_sync(0xffffffffu, ss, off);
    float vv = ss * (1.f / 128.f) + 1.1920929e-07f;
    float inv = rsqrtf(vv);
    inv = inv * (1.5f - 0.5f * vv * inv * inv);  // Newton refine
    row[i0] = o0 * inv;
    row[i1] = o1 * inv;
    row[i0 + 64] = o2 * inv;
    row[i1 + 64] = o3 * inv;
}

// ---------------- windowed gated attention, flash-style, fp32 ----------------
// grid (T/64, H, B), 256 threads; smem: Q 32KB, K 32KB (xor-swizzled), V 32KB, P 16KB
__global__ __launch_bounds__(256) void attn_kernel(const float* __restrict__ Qg,
                                                   const float* __restrict__ Kg,
                                                   const float* __restrict__ Vg,
                                                   const float* __restrict__ cumF,
                                                   float* __restrict__ Y,
                                                   const int* __restrict__ winp)
{
    extern __shared__ float sm[];
    float* Qs = sm;                  // [64][128]
    float* Ks = Qs + 64 * 128;       // [64][128] xor-swizzled float4s
    float* Vs = Ks + 64 * 128;       // [64][128]
    float* Ps = Vs + 64 * 128;       // [64][64]

    const int tid = threadIdx.x;
    const int lane = tid & 31, w = tid >> 5;
    const int qt = blockIdx.x, h = blockIdx.y, b = blockIdx.z;
    const int q0 = qt * 64;
    const int win = *winp;
    const float sm_scale = 0.08838834764831845f;   // 1/sqrt(128)
    const float* cF = cumF + (size_t)(b * PH + h) * PT;

    // Load + pre-scale Q tile
    {
        const size_t base = ((size_t)(b * PT + q0) * PH + h) * PD;
#pragma unroll
        for (int i = 0; i < 8; i++) {
            int idx = tid + 256 * i;           // float4 index 0..2047
            int r = idx >> 5, d4 = idx & 31;
            float4 qv = *(const float4*)&Qg[base + (size_t)r * PHD + d4 * 4];
            qv.x *= sm_scale; qv.y *= sm_scale; qv.z *= sm_scale; qv.w *= sm_scale;
            *(float4*)&Qs[r * 128 + d4 * 4] = qv;
        }
    }
    float cfq[8];
#pragma unroll
    for (int r = 0; r < 8; r++) cfq[r] = cF[q0 + w * 8 + r];

    float m[8], l[8];
    float4 acc[8];
#pragma unroll
    for (int r = 0; r < 8; r++) {
        m[r] = -1e30f; l[r] = 0.f;
        acc[r] = make_float4(0.f, 0.f, 0.f, 0.f);
    }

    int lo = q0 - win + 1;
    int kt_min = lo > 0 ? (lo >> 6) : 0;

    for (int kt = qt; kt >= kt_min; --kt) {
        const int kb = kt * 64;
        __syncthreads();
        {
            const size_t base = ((size_t)(b * PT + kb) * PH + h) * PD;
#pragma unroll
            for (int i = 0; i < 8; i++) {
                int idx = tid + 256 * i;
                int r = idx >> 5, d4 = idx & 31;
                float4 kv = *(const float4*)&Kg[base + (size_t)r * PHD + d4 * 4];
                *(float4*)&Ks[r * 128 + ((d4 ^ (r & 31)) << 2)] = kv;
                float4 vv = *(const float4*)&Vg[base + (size_t)r * PHD + d4 * 4];
                *(float4*)&Vs[r * 128 + d4 * 4] = vv;
            }
        }
        __syncthreads();

        // S = Qs · Ks^T : warp w owns rows w*8..w*8+7; lane owns cols lane, lane+32
        float s0[8], s1[8];
#pragma unroll
        for (int r = 0; r < 8; r++) { s0[r] = 0.f; s1[r] = 0.f; }
        const float* K0row = &Ks[lane * 128];
        const float* K1row = &Ks[(lane + 32) * 128];
#pragma unroll 2
        for (int d4 = 0; d4 < 32; d4++) {
            float4 k0 = *(const float4*)&K0row[(d4 ^ lane) << 2];
            float4 k1 = *(const float4*)&K1row[(d4 ^ lane) << 2];
#pragma unroll
            for (int r = 0; r < 8; r++) {
                float4 qv = *(const float4*)&Qs[(w * 8 + r) * 128 + d4 * 4];
                s0[r] += qv.x * k0.x + qv.y * k0.y + qv.z * k0.z + qv.w * k0.w;
                s1[r] += qv.x * k1.x + qv.y * k1.y + qv.z * k1.z + qv.w * k1.w;
            }
        }

        // bias + mask + online softmax
        const float cfk0 = cF[kb + lane];
        const float cfk1 = cF[kb + lane + 32];
        const int j0 = kb + lane, j1 = j0 + 32;
#pragma unroll
        for (int r = 0; r < 8; r++) {
            const int qi = q0 + w * 8 + r;
            float v0 = (j0 <= qi && qi - j0 < win) ? s0[r] + cfq[r] - cfk0 : -1e30f;
            float v1 = (j1 <= qi && qi - j1 < win) ? s1[r] + cfq[r] - cfk1 : -1e30f;
            float mx = fmaxf(v0, v1);
#pragma unroll
            for (int off = 16; off > 0; off >>= 1)
                mx = fmaxf(mx, __shfl_xor_sync(0xffffffffu, mx, off));
            float mn = fmaxf(m[r], mx);
            float sc = expf(m[r] - mn);
            m[r] = mn;
            float p0 = expf(v0 - mn);
            float p1 = expf(v1 - mn);
            float rs = p0 + p1;
#pragma unroll
            for (int off = 16; off > 0; off >>= 1)
                rs += __shfl_xor_sync(0xffffffffu, rs, off);
            l[r] = l[r] * sc + rs;
            Ps[(w * 8 + r) * 64 + lane] = p0;
            Ps[(w * 8 + r) * 64 + lane + 32] = p1;
            acc[r].x *= sc; acc[r].y *= sc; acc[r].z *= sc; acc[r].w *= sc;
        }
        __syncwarp();

        // acc += P · V : lane owns d = lane*4..lane*4+3
#pragma unroll 2
        for (int k4 = 0; k4 < 64; k4 += 4) {
            float4 v0 = *(const float4*)&Vs[(k4 + 0) * 128 + lane * 4];
            float4 v1 = *(const float4*)&Vs[(k4 + 1) * 128 + lane * 4];
            float4 v2 = *(const float4*)&Vs[(k4 + 2) * 128 + lane * 4];
            float4 v3 = *(const float4*)&Vs[(k4 + 3) * 128 + lane * 4];
#pragma unroll
            for (int r = 0; r < 8; r++) {
                float4 p = *(const float4*)&Ps[(w * 8 + r) * 64 + k4];
                acc[r].x += p.x * v0.x + p.y * v1.x + p.z * v2.x + p.w * v3.x;
                acc[r].y += p.x * v0.y + p.y * v1.y + p.z * v2.y + p.w * v3.y;
                acc[r].z += p.x * v0.z + p.y * v1.z + p.z * v2.z + p.w * v3.z;
                acc[r].w += p.x * v0.w + p.y * v1.w + p.z * v2.w + p.w * v3.w;
            }
        }
        __syncwarp();
    }

    // epilogue: out = acc / l, write [B,T,H,D]
#pragma unroll
    for (int r = 0; r < 8; r++) {
        float inv = 1.f / l[r];
        size_t o = ((size_t)(b * PT + q0 + w * 8 + r) * PH + h) * PD + lane * 4;
        float4 ov = make_float4(acc[r].x * inv, acc[r].y * inv,
                                acc[r].z * inv, acc[r].w * inv);
        *(float4*)&Y[o] = ov;
    }
}

// ---------------- launch ----------------
extern "C" void kernel_launch(void* const* d_in, const int* in_sizes, int n_in,
                              void* d_out, int out_size)
{
    const float* x   = (const float*)d_in[0];
    const float* cosp= (const float*)d_in[1];
    const float* sinp= (const float*)d_in[2];
    const float* Wq  = (const float*)d_in[3];
    const float* Wk  = (const float*)d_in[4];
    const float* Wv  = (const float*)d_in[5];
    const float* Wo  = (const float*)d_in[6];
    const float* fw  = (const float*)d_in[7];
    const float* fb  = (const float*)d_in[8];
    const float* wl  = (const float*)d_in[9];
    const int*   win = (const int*)d_in[10];
    float* out = (float*)d_out;

    float *q, *k, *v, *y, *lf, *cf;
    cudaGetSymbolAddress((void**)&q, g_q);
    cudaGetSymbolAddress((void**)&k, g_k);
    cudaGetSymbolAddress((void**)&v, g_v);
    cudaGetSymbolAddress((void**)&y, g_y);
    cudaGetSymbolAddress((void**)&lf, g_lf);
    cudaGetSymbolAddress((void**)&cf, g_cf);

    dim3 gg(PHD / 128, PM / 128);                 // (16, 32)
    sgemm128<<<gg, 256>>>(x, Wq, q, PM, PHD, PC);
    sgemm128<<<gg, 256>>>(x, Wk, k, PM, PHD, PC);
    sgemm128<<<gg, 256>>>(x, Wv, v, PM, PHD, PC);

    gate_kernel<<<PM, 256>>>(x, fw, fb, wl, lf);
    cumsum_kernel<<<PB * PH, 256>>>(lf, cf);

    rope_rms_kernel<<<(PB * PT * PH) / 8, 256>>>(q, cosp, sinp);
    rope_rms_kernel<<<(PB * PT * PH) / 8, 256>>>(k, cosp, sinp);

    const size_t attn_smem = (size_t)(3 * 64 * 128 + 64 * 64) * sizeof(float); // 114688
    cudaFuncSetAttribute(attn_kernel, cudaFuncAttributeMaxDynamicSharedMemorySize,
                         (int)attn_smem);
    dim3 ag(PT / 64, PH, PB);                     // (32, 16, 2)
    attn_kernel<<<ag, 256, attn_smem>>>(q, k, v, cf, y, win);

    sgemm128<<<gg, 256>>>(y, Wo, out, PM, PC, PC);
}

// round 3
// speedup vs baseline: 2.1488x; 2.1488x over previous
#include <cuda_runtime.h>
#include <cuda_bf16.h>
#include <math.h>

// Problem constants (fixed by setup_inputs)
#define PB 2
#define PT 2048
#define PC 2048
#define PH 16
#define PD 128
#define PM (PB*PT)        // 4096 rows of x
#define PHD (PH*PD)       // 2048

// ---------------- scratch (device globals; no allocs allowed) ----------------
__device__ float g_q[PB*PT*PH*PD];
__device__ float g_k[PB*PT*PH*PD];
__device__ float g_v[PB*PT*PH*PD];
__device__ float g_y[PB*PT*PH*PD];
__device__ float g_lf[PB*PH*PT];
__device__ float g_cf[PB*PH*PT];

// ---------------- tf32 tensor-core GEMM: C[M,N] = A[M,K] @ B[K,N] ------------
// 128x128x32 CTA tile, 8 warps (4 along M x 2 along N), warp tile 32x64,
// mma.sync.m16n8k8 tf32, cp.async double-buffered smem.
#define ASTRIDE 36      // 128 rows x 36 (pad 4): frag reads conflict-free
#define BSTRIDE 136     // 32 rows x 136 (pad 8): frag reads conflict-free
#define ASZ (128*ASTRIDE)
#define BSZ (32*BSTRIDE)
#define TG_SMEM ((2*ASZ + 2*BSZ)*4)   // 71680 bytes

__device__ __forceinline__ unsigned f2tf(float f) {
    unsigned u;
    asm("cvt.rna.tf32.f32 %0, %1;" : "=r"(u) : "f"(f));
    return u;
}

__device__ __forceinline__ void cp16(void* smem_dst, const void* gsrc) {
    unsigned s = (unsigned)__cvta_generic_to_shared(smem_dst);
    asm volatile("cp.async.cg.shared.global [%0], [%1], 16;" :: "r"(s), "l"(gsrc));
}

__global__ __launch_bounds__(256) void tgemm(const float* __restrict__ A,
                                             const float* __restrict__ B,
                                             float* __restrict__ C,
                                             int M, int N, int K)
{
    extern __shared__ float sm[];
    float* As = sm;              // 2 stages of ASZ
    float* Bs = sm + 2 * ASZ;    // 2 stages of BSZ

    const int tid = threadIdx.x;
    const int bm = blockIdx.y * 128, bn = blockIdx.x * 128;
    const int lane = tid & 31, warp = tid >> 5;
    const int wm = (warp & 3) * 32;    // warp offset along M
    const int wn = (warp >> 2) * 64;   // warp offset along N
    const int g = lane >> 2, tg = lane & 3;

    float acc[2][8][4];
#pragma unroll
    for (int mt = 0; mt < 2; mt++)
#pragma unroll
        for (int nt = 0; nt < 8; nt++)
#pragma unroll
            for (int i = 0; i < 4; i++) acc[mt][nt][i] = 0.f;

    // global->smem load mapping (4 float4 per thread for each of A, B)
    const int arow = tid >> 3, ac = (tid & 7) * 4;   // A: rows arow+32i, cols ac..ac+3
    const int brow = tid >> 5, bc = (tid & 31) * 4;  // B: rows brow+8i,  cols bc..bc+3
    const float* Ag = A + (size_t)(bm + arow) * K + ac;
    const float* Bg = B + (size_t)brow * N + bn + bc;

    const int nT = K / 32;

    // prologue: stage 0
    {
#pragma unroll
        for (int i = 0; i < 4; i++)
            cp16(&As[(arow + 32 * i) * ASTRIDE + ac], Ag + (size_t)(32 * i) * K);
#pragma unroll
        for (int i = 0; i < 4; i++)
            cp16(&Bs[(brow + 8 * i) * BSTRIDE + bc], Bg + (size_t)(8 * i) * N);
        asm volatile("cp.async.commit_group;");
    }

    for (int t = 0; t < nT; t++) {
        if (t + 1 < nT) {
            float* Ad = As + ((t + 1) & 1) * ASZ;
            float* Bd = Bs + ((t + 1) & 1) * BSZ;
            const float* Ags = Ag + (t + 1) * 32;
            const float* Bgs = Bg + (size_t)(t + 1) * 32 * N;
#pragma unroll
            for (int i = 0; i < 4; i++)
                cp16(&Ad[(arow + 32 * i) * ASTRIDE + ac], Ags + (size_t)(32 * i) * K);
#pragma unroll
            for (int i = 0; i < 4; i++)
                cp16(&Bd[(brow + 8 * i) * BSTRIDE + bc], Bgs + (size_t)(8 * i) * N);
            asm volatile("cp.async.commit_group;");
            asm volatile("cp.async.wait_group 1;");
        } else {
            asm volatile("cp.async.wait_group 0;");
        }
        __syncthreads();

        const float* Ac = As + (t & 1) * ASZ;
        const float* Bc = Bs + (t & 1) * BSZ;

#pragma unroll
        for (int kk = 0; kk < 32; kk += 8) {
            unsigned af[2][4];
#pragma unroll
            for (int mt = 0; mt < 2; mt++) {
                const int r0 = wm + mt * 16 + g;
                af[mt][0] = f2tf(Ac[(r0)     * ASTRIDE + kk + tg]);
                af[mt][1] = f2tf(Ac[(r0 + 8) * ASTRIDE + kk + tg]);
                af[mt][2] = f2tf(Ac[(r0)     * ASTRIDE + kk + tg + 4]);
                af[mt][3] = f2tf(Ac[(r0 + 8) * ASTRIDE + kk + tg + 4]);
            }
#pragma unroll
            for (int nt = 0; nt < 8; nt++) {
                const int n = wn + nt * 8 + g;
                unsigned b0 = f2tf(Bc[(kk + tg)     * BSTRIDE + n]);
                unsigned b1 = f2tf(Bc[(kk + tg + 4) * BSTRIDE + n]);
#pragma unroll
                for (int mt = 0; mt < 2; mt++) {
                    asm volatile(
                        "mma.sync.aligned.m16n8k8.row.col.f32.tf32.tf32.f32 "
                        "{%0,%1,%2,%3}, {%4,%5,%6,%7}, {%8,%9}, {%0,%1,%2,%3};"
                        : "+f"(acc[mt][nt][0]), "+f"(acc[mt][nt][1]),
                          "+f"(acc[mt][nt][2]), "+f"(acc[mt][nt][3])
                        : "r"(af[mt][0]), "r"(af[mt][1]),
                          "r"(af[mt][2]), "r"(af[mt][3]),
                          "r"(b0), "r"(b1));
                }
            }
        }
        __syncthreads();
    }

    // epilogue: c0,c1 -> (row, 2tg..2tg+1); c2,c3 -> row+8
#pragma unroll
    for (int mt = 0; mt < 2; mt++) {
#pragma unroll
        for (int nt = 0; nt < 8; nt++) {
            const int row0 = bm + wm + mt * 16 + g;
            const int col = bn + wn + nt * 8 + 2 * tg;
            *(float2*)&C[(size_t)row0 * N + col] =
                make_float2(acc[mt][nt][0], acc[mt][nt][1]);
            *(float2*)&C[(size_t)(row0 + 8) * N + col] =
                make_float2(acc[mt][nt][2], acc[mt][nt][3]);
        }
    }
}

// ---------------- gate kernel: lam/logit/log_fgate per (b,t,h) ----------------
__global__ __launch_bounds__(256) void gate_kernel(const float* __restrict__ x,
                                                   const float* __restrict__ fw,
                                                   const float* __restrict__ fb,
                                                   const float* __restrict__ wl,
                                                   float* __restrict__ lf)
{
    __shared__ float xs[2048];
    __shared__ float red[256];
    __shared__ float dots[32];
    const int bt = blockIdx.x;
    const int tid = threadIdx.x;
    const float* xr = x + (size_t)bt * PC;
#pragma unroll
    for (int i = 0; i < 2; i++)
        *(float4*)&xs[(tid + 256 * i) * 4] = *(const float4*)&xr[(tid + 256 * i) * 4];
    __syncthreads();

    const int g = tid >> 5, o = tid & 31;
    const float* W = (o < 16) ? fw : wl;
    const int h = o & 15;
    float s = 0.f;
    for (int c = g; c < PC; c += 8) s += xs[c] * W[c * PH + h];
    red[tid] = s;
    __syncthreads();
    if (tid < 32) {
        float t = red[tid];
#pragma unroll
        for (int g2 = 1; g2 < 8; g2++) t += red[tid + 32 * g2];
        dots[tid] = t;
    }
    __syncthreads();
    if (tid < 16) {
        const int b = bt >> 11;       // /T
        const int t = bt & (PT - 1);
        float fdot = dots[tid] + fb[tid];
        float ldot = dots[16 + tid];
        float lam = ldot > 0.f ? ldot + 1.f : expf(ldot);  // elu(x)+1
        float logit = fdot * lam;
        float ls = (logit >= 0.f) ? -log1pf(expf(-logit))
                                  : (logit - log1pf(expf(logit)));
        lf[((size_t)(b * PH + tid)) * PT + t] = ls / (lam + 0.001f);
    }
}

// ---------------- cumsum over T per (b,h) ----------------
__global__ __launch_bounds__(256) void cumsum_kernel(const float* __restrict__ lf,
                                                     float* __restrict__ cf)
{
    __shared__ float tot[256];
    const int bh = blockIdx.x, tid = threadIdx.x;
    const float* in = lf + (size_t)bh * PT;
    float* out = cf + (size_t)bh * PT;
    float v[8];
    float r = 0.f;
#pragma unroll
    for (int j = 0; j < 8; j++) { r += in[tid * 8 + j]; v[j] = r; }
    tot[tid] = r;
    __syncthreads();
    for (int off = 1; off < 256; off <<= 1) {
        float t = 0.f;
        if (tid >= off) t = tot[tid - off];
        __syncthreads();
        if (tid >= off) tot[tid] += t;
        __syncthreads();
    }
    float base = tid ? tot[tid - 1] : 0.f;
#pragma unroll
    for (int j = 0; j < 8; j++) out[tid * 8 + j] = v[j] + base;
}

// ---------------- RoPE + RMSNorm, in place on [B,T,H,D] ----------------
__global__ __launch_bounds__(256) void rope_rms_kernel(float* __restrict__ data,
                                                       const float* __restrict__ cosp,
                                                       const float* __restrict__ sinp)
{
    const int wid = blockIdx.x * 8 + (threadIdx.x >> 5);   // (b,t,h) index
    const int lane = threadIdx.x & 31;
    const int t = (wid >> 4) & (PT - 1);
    float* row = data + (size_t)wid * PD;
    const int i0 = lane, i1 = lane + 32;
    float x1a = row[i0], x1b = row[i1];
    float x2a = row[i0 + 64], x2b = row[i1 + 64];
    float ca = cosp[t * 64 + i0], cb = cosp[t * 64 + i1];
    float sa = sinp[t * 64 + i0], sb = sinp[t * 64 + i1];
    float o0 = x1a * ca + x2a * sa;
    float o1 = x1b * cb + x2b * sb;
    float o2 = x2a * ca - x1a * sa;
    float o3 = x2b * cb - x1b * sb;
    float ss = o0 * o0 + o1 * o1 + o2 * o2 + o3 * o3;
#pragma unroll
    for (int off = 16; off > 0; off >>= 1) ss += __shfl_xor_sync(0xffffffffu, ss, off);
    float vv = ss * (1.f / 128.f) + 1.1920929e-07f;
    float inv = rsqrtf(vv);
    inv = inv * (1.5f - 0.5f * vv * inv * inv);  // Newton refine
    row[i0] = o0 * inv;
    row[i1] = o1 * inv;
    row[i0 + 64] = o2 * inv;
    row[i1 + 64] = o3 * inv;
}

// ---------------- windowed gated attention, flash-style, fp32 ----------------
// grid (T/64, H, B), 256 threads; smem: Q 32KB, K 32KB (xor-swizzled), V 32KB, P 16KB
__global__ __launch_bounds__(256) void attn_kernel(const float* __restrict__ Qg,
                                                   const float* __restrict__ Kg,
                                                   const float* __restrict__ Vg,
                                                   const float* __restrict__ cumF,
                                                   float* __restrict__ Y,
                                                   const int* __restrict__ winp)
{
    extern __shared__ float smA[];
    float* Qs = smA;                 // [64][128]
    float* Ks = Qs + 64 * 128;       // [64][128] xor-swizzled float4s
    float* Vs = Ks + 64 * 128;       // [64][128]
    float* Ps = Vs + 64 * 128;       // [64][64]

    const int tid = threadIdx.x;
    const int lane = tid & 31, w = tid >> 5;
    const int qt = blockIdx.x, h = blockIdx.y, b = blockIdx.z;
    const int q0 = qt * 64;
    const int win = *winp;
    const float sm_scale = 0.08838834764831845f;   // 1/sqrt(128)
    const float* cF = cumF + (size_t)(b * PH + h) * PT;

    // Load + pre-scale Q tile
    {
        const size_t base = ((size_t)(b * PT + q0) * PH + h) * PD;
#pragma unroll
        for (int i = 0; i < 8; i++) {
            int idx = tid + 256 * i;           // float4 index 0..2047
            int r = idx >> 5, d4 = idx & 31;
            float4 qv = *(const float4*)&Qg[base + (size_t)r * PHD + d4 * 4];
            qv.x *= sm_scale; qv.y *= sm_scale; qv.z *= sm_scale; qv.w *= sm_scale;
            *(float4*)&Qs[r * 128 + d4 * 4] = qv;
        }
    }
    float cfq[8];
#pragma unroll
    for (int r = 0; r < 8; r++) cfq[r] = cF[q0 + w * 8 + r];

    float m[8], l[8];
    float4 acc[8];
#pragma unroll
    for (int r = 0; r < 8; r++) {
        m[r] = -1e30f; l[r] = 0.f;
        acc[r] = make_float4(0.f, 0.f, 0.f, 0.f);
    }

    int lo = q0 - win + 1;
    int kt_min = lo > 0 ? (lo >> 6) : 0;

    for (int kt = qt; kt >= kt_min; --kt) {
        const int kb = kt * 64;
        __syncthreads();
        {
            const size_t base = ((size_t)(b * PT + kb) * PH + h) * PD;
#pragma unroll
            for (int i = 0; i < 8; i++) {
                int idx = tid + 256 * i;
                int r = idx >> 5, d4 = idx & 31;
                float4 kv = *(const float4*)&Kg[base + (size_t)r * PHD + d4 * 4];
                *(float4*)&Ks[r * 128 + ((d4 ^ (r & 31)) << 2)] = kv;
                float4 vv = *(const float4*)&Vg[base + (size_t)r * PHD + d4 * 4];
                *(float4*)&Vs[r * 128 + d4 * 4] = vv;
            }
        }
        __syncthreads();

        // S = Qs · Ks^T : warp w owns rows w*8..w*8+7; lane owns cols lane, lane+32
        float s0[8], s1[8];
#pragma unroll
        for (int r = 0; r < 8; r++) { s0[r] = 0.f; s1[r] = 0.f; }
        const float* K0row = &Ks[lane * 128];
        const float* K1row = &Ks[(lane + 32) * 128];
#pragma unroll 2
        for (int d4 = 0; d4 < 32; d4++) {
            float4 k0 = *(const float4*)&K0row[(d4 ^ lane) << 2];
            float4 k1 = *(const float4*)&K1row[(d4 ^ lane) << 2];
#pragma unroll
            for (int r = 0; r < 8; r++) {
                float4 qv = *(const float4*)&Qs[(w * 8 + r) * 128 + d4 * 4];
                s0[r] += qv.x * k0.x + qv.y * k0.y + qv.z * k0.z + qv.w * k0.w;
                s1[r] += qv.x * k1.x + qv.y * k1.y + qv.z * k1.z + qv.w * k1.w;
            }
        }

        // bias + mask + online softmax
        const float cfk0 = cF[kb + lane];
        const float cfk1 = cF[kb + lane + 32];
        const int j0 = kb + lane, j1 = j0 + 32;
#pragma unroll
        for (int r = 0; r < 8; r++) {
            const int qi = q0 + w * 8 + r;
            float v0 = (j0 <= qi && qi - j0 < win) ? s0[r] + cfq[r] - cfk0 : -1e30f;
            float v1 = (j1 <= qi && qi - j1 < win) ? s1[r] + cfq[r] - cfk1 : -1e30f;
            float mx = fmaxf(v0, v1);
#pragma unroll
            for (int off = 16; off > 0; off >>= 1)
                mx = fmaxf(mx, __shfl_xor_sync(0xffffffffu, mx, off));
            float mn = fmaxf(m[r], mx);
            float sc = expf(m[r] - mn);
            m[r] = mn;
            float p0 = expf(v0 - mn);
            float p1 = expf(v1 - mn);
            float rs = p0 + p1;
#pragma unroll
            for (int off = 16; off > 0; off >>= 1)
                rs += __shfl_xor_sync(0xffffffffu, rs, off);
            l[r] = l[r] * sc + rs;
            Ps[(w * 8 + r) * 64 + lane] = p0;
            Ps[(w * 8 + r) * 64 + lane + 32] = p1;
            acc[r].x *= sc; acc[r].y *= sc; acc[r].z *= sc; acc[r].w *= sc;
        }
        __syncwarp();

        // acc += P · V : lane owns d = lane*4..lane*4+3
#pragma unroll 2
        for (int k4 = 0; k4 < 64; k4 += 4) {
            float4 v0 = *(const float4*)&Vs[(k4 + 0) * 128 + lane * 4];
            float4 v1 = *(const float4*)&Vs[(k4 + 1) * 128 + lane * 4];
            float4 v2 = *(const float4*)&Vs[(k4 + 2) * 128 + lane * 4];
            float4 v3 = *(const float4*)&Vs[(k4 + 3) * 128 + lane * 4];
#pragma unroll
            for (int r = 0; r < 8; r++) {
                float4 p = *(const float4*)&Ps[(w * 8 + r) * 64 + k4];
                acc[r].x += p.x * v0.x + p.y * v1.x + p.z * v2.x + p.w * v3.x;
                acc[r].y += p.x * v0.y + p.y * v1.y + p.z * v2.y + p.w * v3.y;
                acc[r].z += p.x * v0.z + p.y * v1.z + p.z * v2.z + p.w * v3.z;
                acc[r].w += p.x * v0.w + p.y * v1.w + p.z * v2.w + p.w * v3.w;
            }
        }
        __syncwarp();
    }

    // epilogue: out = acc / l, write [B,T,H,D]
#pragma unroll
    for (int r = 0; r < 8; r++) {
        float inv = 1.f / l[r];
        size_t o = ((size_t)(b * PT + q0 + w * 8 + r) * PH + h) * PD + lane * 4;
        float4 ov = make_float4(acc[r].x * inv, acc[r].y * inv,
                                acc[r].z * inv, acc[r].w * inv);
        *(float4*)&Y[o] = ov;
    }
}

// ---------------- launch ----------------
extern "C" void kernel_launch(void* const* d_in, const int* in_sizes, int n_in,
                              void* d_out, int out_size)
{
    const float* x   = (const float*)d_in[0];
    const float* cosp= (const float*)d_in[1];
    const float* sinp= (const float*)d_in[2];
    const float* Wq  = (const float*)d_in[3];
    const float* Wk  = (const float*)d_in[4];
    const float* Wv  = (const float*)d_in[5];
    const float* Wo  = (const float*)d_in[6];
    const float* fw  = (const float*)d_in[7];
    const float* fb  = (const float*)d_in[8];
    const float* wl  = (const float*)d_in[9];
    const int*   win = (const int*)d_in[10];
    float* out = (float*)d_out;

    float *q, *k, *v, *y, *lf, *cf;
    cudaGetSymbolAddress((void**)&q, g_q);
    cudaGetSymbolAddress((void**)&k, g_k);
    cudaGetSymbolAddress((void**)&v, g_v);
    cudaGetSymbolAddress((void**)&y, g_y);
    cudaGetSymbolAddress((void**)&lf, g_lf);
    cudaGetSymbolAddress((void**)&cf, g_cf);

    cudaFuncSetAttribute(tgemm, cudaFuncAttributeMaxDynamicSharedMemorySize, TG_SMEM);

    dim3 gg(PHD / 128, PM / 128);                 // (16, 32)
    tgemm<<<gg, 256, TG_SMEM>>>(x, Wq, q, PM, PHD, PC);
    tgemm<<<gg, 256, TG_SMEM>>>(x, Wk, k, PM, PHD, PC);
    tgemm<<<gg, 256, TG_SMEM>>>(x, Wv, v, PM, PHD, PC);

    gate_kernel<<<PM, 256>>>(x, fw, fb, wl, lf);
    cumsum_kernel<<<PB * PH, 256>>>(lf, cf);

    rope_rms_kernel<<<(PB * PT * PH) / 8, 256>>>(q, cosp, sinp);
    rope_rms_kernel<<<(PB * PT * PH) / 8, 256>>>(k, cosp, sinp);

    const size_t attn_smem = (size_t)(3 * 64 * 128 + 64 * 64) * sizeof(float); // 114688
    cudaFuncSetAttribute(attn_kernel, cudaFuncAttributeMaxDynamicSharedMemorySize,
                         (int)attn_smem);
    dim3 ag(PT / 64, PH, PB);                     // (32, 16, 2)
    attn_kernel<<<ag, 256, attn_smem>>>(q, k, v, cf, y, win);

    tgemm<<<gg, 256, TG_SMEM>>>(y, Wo, out, PM, PC, PC);
}